// round 14
// baseline (speedup 1.0000x reference)
#include <cuda_runtime.h>

#define NBOX 4096
#define T 1024
#define PER 4                  // NBOX / T
#define NWARP 32
#define PROD (NWARP - 1)       // producer = HIGHEST wid (hi-wid-first arbiter)
#define BMAX 64
#define THRESH 0.05f
#define FULL 0xffffffffu

__device__ float4 g_sbox[NBOX];
__device__ int    g_orig[NBOX];

__global__ __launch_bounds__(T, 1)
void softnms_kernel(const float4* __restrict__ boxes,
                    const float*  __restrict__ scores,
                    float* __restrict__ out, int out_size)
{
    __shared__ unsigned long long skv[NBOX];   // sort scratch
    __shared__ uint4    spoolA[NWARP];         // (k1, p1, k2, p2) exact keys
    __shared__ unsigned sm3[NWARP];            // per-warp 3rd-best value
    __shared__ float4   sbatch_box[BMAX];
    __shared__ uint2    sbatch_meta[BMAX];     // (sorted pos, exact score bits)
    __shared__ int      sB, sfro, sfpos;

    const int t    = threadIdx.x;
    const int lane = t & 31;
    const int wid  = t >> 5;

    // ---- init: zero score outputs, stage u64 sort keys ----
#pragma unroll
    for (int k = 0; k < PER; k++) {
        const int gi = t * PER + k;
        if (gi < out_size) out[gi] = 0.0f;
        skv[gi] = ((unsigned long long)__float_as_uint(boxes[gi].x) << 32)
                  | (unsigned)gi;
    }
    __syncthreads();

    // ---- bitonic sort ascending by x1 ----
    for (int k = 2; k <= NBOX; k <<= 1) {
        for (int j = k >> 1; j > 0; j >>= 1) {
#pragma unroll
            for (int e = t; e < NBOX; e += T) {
                const int ixj = e ^ j;
                if (ixj > e) {
                    const unsigned long long a = skv[e], c = skv[ixj];
                    const bool up = ((e & k) == 0);
                    if (up ? (a > c) : (a < c)) { skv[e] = c; skv[ixj] = a; }
                }
            }
            __syncthreads();
        }
    }

    // ---- load my PER sorted boxes; publish sorted tables ----
    float x1[PER], y1[PER], x2[PER], y2[PER], area[PER], s[PER];
    int   orig[PER];
    unsigned procm = 0;
    float tx2hi = 0.0f;
#pragma unroll
    for (int k = 0; k < PER; k++) {
        const int pos = t * PER + k;
        const int o   = (int)(unsigned)(skv[pos] & 0xffffffffu);
        orig[k] = o;
        const float4 b = boxes[o];
        x1[k] = b.x; y1[k] = b.y; x2[k] = b.z; y2[k] = b.w;
        area[k] = (b.z - b.x) * (b.w - b.y);
        s[k]    = scores[o];
        g_sbox[pos] = b;
        g_orig[pos] = o;
        tx2hi = fmaxf(tx2hi, b.z);
    }
    const float tx1lo = x1[0];
    // warp-level x-window (x coords > 0 -> float bits monotone)
    const float wx1lo = __shfl_sync(FULL, tx1lo, 0);
    const float wx2hi = __uint_as_float(
        __reduce_max_sync(FULL, __float_as_uint(tx2hi)));
    __syncthreads();

    bool dirty = true;
    int  step  = 0;
    int  fro_final = 0, fpos_final = 0;

    while (step < NBOX) {
        // ========= rebuild per-warp top-2 (+3rd value), EXACT argmax =======
        if (__ballot_sync(FULL, dirty)) {
            unsigned b1 = 0, b2 = 0, b3 = 0, p1 = 0, p2 = 0;
#pragma unroll
            for (int k = 0; k < PER; k++) {
                if (!((procm >> k) & 1u)) {
                    const unsigned ub = __float_as_uint(s[k]);   // scores > 0
                    const unsigned up = (unsigned)(t * PER + k);
                    if (ub > b1)      { b3 = b2; b2 = b1; p2 = p1; b1 = ub; p1 = up; }
                    else if (ub > b2) { b3 = b2; b2 = ub; p2 = up; }
                    else if (ub > b3) { b3 = ub; }
                }
            }
            const unsigned m1   = __reduce_max_sync(FULL, b1);
            const unsigned bal1 = __ballot_sync(FULL, b1 == m1);
            const int s1        = __ffs(bal1) - 1;
            const unsigned q1   = __shfl_sync(FULL, p1, s1);
            const unsigned v2   = (lane == s1) ? b2 : b1;
            const unsigned vp2  = (lane == s1) ? p2 : p1;
            const unsigned m2   = __reduce_max_sync(FULL, v2);
            const unsigned bal2 = __ballot_sync(FULL, v2 == m2);
            const int s2        = __ffs(bal2) - 1;
            const unsigned q2   = __shfl_sync(FULL, vp2, s2);
            unsigned v3 = b1;
            if (lane == s1) v3 = b2;
            if (lane == s2) v3 = (s2 == s1) ? b3 : b2;
            const unsigned m3 = __reduce_max_sync(FULL, v3);
            if (lane == 0) { spoolA[wid] = make_uint4(m1, q1, m2, q2); sm3[wid] = m3; }
            dirty = false;
        }
        __syncthreads();   // bar1: pools visible; consumers park in bar2 next

        if (wid == PROD) {
            // ==== producer scans ALONE on a quiet SM (others sit in BAR) ===
            const uint4 a = spoolA[lane];
            unsigned k1 = a.x, pp1 = a.y, k2 = a.z, pp2 = a.w;
            const unsigned M3 = __reduce_max_sync(FULL, sm3[lane]);
            const float4 f1 = g_sbox[pp1]; const float a1 = (f1.z - f1.x) * (f1.w - f1.y);
            const float4 f2 = g_sbox[pp2]; const float a2 = (f2.z - f2.x) * (f2.w - f2.y);
            const unsigned THRESH_BITS = __float_as_uint(THRESH);

            int B = 0, fz = 0; unsigned fp = 0;
            while (true) {
                const bool s1w      = (k1 >= k2);
                const unsigned kmax = s1w ? k1 : k2;
                const unsigned m    = __reduce_max_sync(FULL, kmax);
                if (m < M3) break;                   // pool no longer covers order
                const unsigned bal = __ballot_sync(FULL, kmax == m);
                const int src      = __ffs(bal) - 1;
                if (m <= THRESH_BITS) {              // pool max == global max
                    fz = 1;
                    fp = __shfl_sync(FULL, s1w ? pp1 : pp2, src);
                    break;
                }
                const float mx1 = __shfl_sync(FULL, s1w ? f1.x : f2.x, src);
                const float my1 = __shfl_sync(FULL, s1w ? f1.y : f2.y, src);
                const float mx2 = __shfl_sync(FULL, s1w ? f1.z : f2.z, src);
                const float my2 = __shfl_sync(FULL, s1w ? f1.w : f2.w, src);
                const float mar = (mx2 - mx1) * (my2 - my1);
                const bool is_src = (lane == src);
                if (is_src) {                        // plain STS; bar2 publishes
                    sbatch_box[B]  = make_float4(mx1, my1, mx2, my2);
                    sbatch_meta[B] = make_uint2(s1w ? pp1 : pp2, m);
                }
                // consume winner slot (0 stays 0 through decays)
                k1 = (is_src &&  s1w) ? 0u : k1;
                k2 = (is_src && !s1w) ? 0u : k2;
                // unconditional bit-exact decay (inter==0 -> multiply by 1.0f)
                {
                    const float iw = fmaxf(fminf(mx2, f1.z) - fmaxf(mx1, f1.x), 0.0f);
                    const float ih = fmaxf(fminf(my2, f1.w) - fmaxf(my1, f1.y), 0.0f);
                    const float inter = iw * ih;
                    const float iou = __fdividef(inter, mar + a1 - inter);
                    k1 = __float_as_uint(__uint_as_float(k1) * __expf(-2.0f * iou * iou));
                }
                {
                    const float iw = fmaxf(fminf(mx2, f2.z) - fmaxf(mx1, f2.x), 0.0f);
                    const float ih = fmaxf(fminf(my2, f2.w) - fmaxf(my1, f2.y), 0.0f);
                    const float inter = iw * ih;
                    const float iou = __fdividef(inter, mar + a2 - inter);
                    k2 = __float_as_uint(__uint_as_float(k2) * __expf(-2.0f * iou * iou));
                }
                B++;
                if (B == BMAX) break;
            }
            __syncwarp();                            // all lanes' STS done
            if (lane == 0) { sB = B; sfro = fz; sfpos = (int)fp; }
        }
        __syncthreads();   // bar2: batch + flags visible to everyone

        const int B = sB;

        // ---- parallel idxs writes: thread j handles member j ----
        if (t < B && (NBOX + step + t) < out_size)
            out[NBOX + step + t] = (float)g_orig[sbatch_meta[t].x];

        // ---- warp-collective member prefilter (x-window), then mask walk --
        unsigned mask_lo, mask_hi;
        {
            bool p0 = false, p1 = false;
            if (lane < B) {
                const float4 mb = sbatch_box[lane];
                p0 = (mb.x <= wx2hi) && (mb.z >= wx1lo);
            }
            if (lane + 32 < B) {
                const float4 mb = sbatch_box[lane + 32];
                p1 = (mb.x <= wx2hi) && (mb.z >= wx1lo);
            }
            mask_lo = __ballot_sync(FULL, p0);
            mask_hi = __ballot_sync(FULL, p1);
        }
#pragma unroll 1
        for (int half = 0; half < 2; half++) {
            unsigned msk  = half ? mask_hi : mask_lo;   // warp-uniform
            const int bse = half ? 32 : 0;
            while (msk) {
                const int j = __ffs(msk) - 1 + bse;
                msk &= msk - 1;
                const float4 mb = sbatch_box[j];        // LDS broadcast
                const uint2  mm = sbatch_meta[j];
                if (mb.x <= tx2hi && mb.z >= tx1lo) {   // thread window (exact)
                    const float mar = (mb.z - mb.x) * (mb.w - mb.y);
#pragma unroll
                    for (int k = 0; k < PER; k++) {
                        if ((procm >> k) & 1u) continue;
                        if (t * PER + k == (int)mm.x) {
                            procm |= 1u << k;
                            if (orig[k] < out_size) out[orig[k]] = __uint_as_float(mm.y);
                            dirty = true;
                        } else {
                            const float iw = fmaxf(fminf(mb.z, x2[k]) - fmaxf(mb.x, x1[k]), 0.0f);
                            const float ih = fmaxf(fminf(mb.w, y2[k]) - fmaxf(mb.y, y1[k]), 0.0f);
                            const float inter = iw * ih;
                            if (inter > 0.0f) {
                                const float iou = __fdividef(inter, mar + area[k] - inter);
                                s[k] *= __expf(-2.0f * iou * iou);
                                dirty = true;
                            }
                        }
                    }
                }
            }
        }
        step += B;
        if (sfro) { fro_final = 1; fpos_final = sfpos; break; }
    }

    // ---- frozen tail: all remaining steps re-select the same argmax ----
    if (fro_final && step < NBOX) {
        const int fo = g_orig[fpos_final];
        for (int j = step + t; j < NBOX; j += T) {
            if ((NBOX + j) < out_size) out[NBOX + j] = (float)fo;
        }
    }
}

extern "C" void kernel_launch(void* const* d_in, const int* in_sizes, int n_in,
                              void* d_out, int out_size)
{
    const float4* boxes;
    const float*  scores;
    if (in_sizes[0] == 4 * NBOX) {
        boxes  = (const float4*)d_in[0];
        scores = (const float*)d_in[1];
    } else {
        boxes  = (const float4*)d_in[1];
        scores = (const float*)d_in[0];
    }
    softnms_kernel<<<1, T>>>(boxes, scores, (float*)d_out, out_size);
}

// round 15
// speedup vs baseline: 1.0098x; 1.0098x over previous
#include <cuda_runtime.h>

#define NBOX 4096
#define T 1024
#define PER 4                  // NBOX / T
#define NWARP 32
#define PROD (NWARP - 1)       // producer = HIGHEST wid (hi-wid-first arbiter)
#define BMAX 64
#define THRESH 0.05f
#define FULL 0xffffffffu
#define XBUCKETS 16.0f

__device__ float4 g_sbox[NBOX];
__device__ int    g_orig[NBOX];

__global__ __launch_bounds__(T, 1)
void softnms_kernel(const float4* __restrict__ boxes,
                    const float*  __restrict__ scores,
                    float* __restrict__ out, int out_size)
{
    __shared__ unsigned long long skv[NBOX];   // sort scratch
    __shared__ uint4    spoolA[NWARP];         // (k1, p1, k2, p2) exact keys
    __shared__ unsigned sm3[NWARP];            // per-warp 3rd-best value
    __shared__ float4   sbatch_box[BMAX];
    __shared__ uint2    sbatch_meta[BMAX];     // (sorted pos, exact score bits)
    __shared__ int      sB, sfro, sfpos;

    const int t    = threadIdx.x;
    const int lane = t & 31;
    const int wid  = t >> 5;

    // ---- init: zero score outputs, stage (x-bucket, y1, idx) sort keys ----
#pragma unroll
    for (int k = 0; k < PER; k++) {
        const int gi = t * PER + k;
        if (gi < out_size) out[gi] = 0.0f;
        const float4 b = boxes[gi];
        unsigned bucket = (unsigned)(b.x * (XBUCKETS / 801.0f));
        if (bucket > 15u) bucket = 15u;
        // key: bucket[48+] | y1bits[16..47] | idx[0..15]  (y1 >= 0: monotone)
        skv[gi] = ((unsigned long long)bucket << 48)
                | ((unsigned long long)__float_as_uint(b.y) << 16)
                | (unsigned)gi;
    }
    __syncthreads();

    // ---- bitonic sort ascending on composite spatial key ----
    for (int k = 2; k <= NBOX; k <<= 1) {
        for (int j = k >> 1; j > 0; j >>= 1) {
#pragma unroll
            for (int e = t; e < NBOX; e += T) {
                const int ixj = e ^ j;
                if (ixj > e) {
                    const unsigned long long a = skv[e], c = skv[ixj];
                    const bool up = ((e & k) == 0);
                    if (up ? (a > c) : (a < c)) { skv[e] = c; skv[ixj] = a; }
                }
            }
            __syncthreads();
        }
    }

    // ---- load my PER sorted boxes; publish sorted tables ----
    float x1[PER], y1[PER], x2[PER], y2[PER], area[PER], s[PER];
    int   orig[PER];
    unsigned procm = 0;
    float tx1lo = 1e30f, ty1lo = 1e30f, tx2hi = -1e30f, ty2hi = -1e30f;
#pragma unroll
    for (int k = 0; k < PER; k++) {
        const int pos = t * PER + k;
        const int o   = (int)(unsigned)(skv[pos] & 0xffffu);
        orig[k] = o;
        const float4 b = boxes[o];
        x1[k] = b.x; y1[k] = b.y; x2[k] = b.z; y2[k] = b.w;
        area[k] = (b.z - b.x) * (b.w - b.y);
        s[k]    = scores[o];
        g_sbox[pos] = b;
        g_orig[pos] = o;
        tx1lo = fminf(tx1lo, b.x); ty1lo = fminf(ty1lo, b.y);
        tx2hi = fmaxf(tx2hi, b.z); ty2hi = fmaxf(ty2hi, b.w);
    }
    __syncthreads();

    bool dirty = true;
    int  step  = 0;
    int  fro_final = 0, fpos_final = 0;

    while (step < NBOX) {
        // ========= rebuild per-warp top-2 (+3rd value), EXACT argmax =======
        if (__ballot_sync(FULL, dirty)) {
            unsigned b1 = 0, b2 = 0, b3 = 0, p1 = 0, p2 = 0;
#pragma unroll
            for (int k = 0; k < PER; k++) {
                if (!((procm >> k) & 1u)) {
                    const unsigned ub = __float_as_uint(s[k]);   // scores > 0
                    const unsigned up = (unsigned)(t * PER + k);
                    if (ub > b1)      { b3 = b2; b2 = b1; p2 = p1; b1 = ub; p1 = up; }
                    else if (ub > b2) { b3 = b2; b2 = ub; p2 = up; }
                    else if (ub > b3) { b3 = ub; }
                }
            }
            const unsigned m1   = __reduce_max_sync(FULL, b1);
            const unsigned bal1 = __ballot_sync(FULL, b1 == m1);
            const int s1        = __ffs(bal1) - 1;
            const unsigned q1   = __shfl_sync(FULL, p1, s1);
            const unsigned v2   = (lane == s1) ? b2 : b1;
            const unsigned vp2  = (lane == s1) ? p2 : p1;
            const unsigned m2   = __reduce_max_sync(FULL, v2);
            const unsigned bal2 = __ballot_sync(FULL, v2 == m2);
            const int s2        = __ffs(bal2) - 1;
            const unsigned q2   = __shfl_sync(FULL, vp2, s2);
            unsigned v3 = b1;
            if (lane == s1) v3 = b2;
            if (lane == s2) v3 = (s2 == s1) ? b3 : b2;
            const unsigned m3 = __reduce_max_sync(FULL, v3);
            if (lane == 0) { spoolA[wid] = make_uint4(m1, q1, m2, q2); sm3[wid] = m3; }
            dirty = false;
        }
        __syncthreads();   // bar1: pools visible; consumers park in bar2 next

        if (wid == PROD) {
            // ==== producer scans ALONE on a quiet SM (others sit in BAR) ===
            const uint4 a = spoolA[lane];
            unsigned k1 = a.x, pp1 = a.y, k2 = a.z, pp2 = a.w;
            const unsigned M3 = __reduce_max_sync(FULL, sm3[lane]);
            const float4 f1 = g_sbox[pp1]; const float a1 = (f1.z - f1.x) * (f1.w - f1.y);
            const float4 f2 = g_sbox[pp2]; const float a2 = (f2.z - f2.x) * (f2.w - f2.y);
            const unsigned THRESH_BITS = __float_as_uint(THRESH);

            int B = 0, fz = 0; unsigned fp = 0;
            while (true) {
                const bool s1w      = (k1 >= k2);
                const unsigned kmax = s1w ? k1 : k2;
                const unsigned m    = __reduce_max_sync(FULL, kmax);
                if (m < M3) break;                   // pool no longer covers order
                const unsigned bal = __ballot_sync(FULL, kmax == m);
                const int src      = __ffs(bal) - 1;
                if (m <= THRESH_BITS) {              // pool max == global max
                    fz = 1;
                    fp = __shfl_sync(FULL, s1w ? pp1 : pp2, src);
                    break;
                }
                const float mx1 = __shfl_sync(FULL, s1w ? f1.x : f2.x, src);
                const float my1 = __shfl_sync(FULL, s1w ? f1.y : f2.y, src);
                const float mx2 = __shfl_sync(FULL, s1w ? f1.z : f2.z, src);
                const float my2 = __shfl_sync(FULL, s1w ? f1.w : f2.w, src);
                const float mar = (mx2 - mx1) * (my2 - my1);
                const bool is_src = (lane == src);
                if (is_src) {                        // plain STS; bar2 publishes
                    sbatch_box[B]  = make_float4(mx1, my1, mx2, my2);
                    sbatch_meta[B] = make_uint2(s1w ? pp1 : pp2, m);
                }
                // consume winner slot (0 stays 0 through decays)
                k1 = (is_src &&  s1w) ? 0u : k1;
                k2 = (is_src && !s1w) ? 0u : k2;
                // unconditional bit-exact decay (inter==0 -> multiply by 1.0f)
                {
                    const float iw = fmaxf(fminf(mx2, f1.z) - fmaxf(mx1, f1.x), 0.0f);
                    const float ih = fmaxf(fminf(my2, f1.w) - fmaxf(my1, f1.y), 0.0f);
                    const float inter = iw * ih;
                    const float iou = __fdividef(inter, mar + a1 - inter);
                    k1 = __float_as_uint(__uint_as_float(k1) * __expf(-2.0f * iou * iou));
                }
                {
                    const float iw = fmaxf(fminf(mx2, f2.z) - fmaxf(mx1, f2.x), 0.0f);
                    const float ih = fmaxf(fminf(my2, f2.w) - fmaxf(my1, f2.y), 0.0f);
                    const float inter = iw * ih;
                    const float iou = __fdividef(inter, mar + a2 - inter);
                    k2 = __float_as_uint(__uint_as_float(k2) * __expf(-2.0f * iou * iou));
                }
                B++;
                if (B == BMAX) break;
            }
            if (lane == 0) { sB = B; sfro = fz; sfpos = (int)fp; }
        }
        __syncthreads();   // bar2: batch + flags visible to everyone

        const int B = sB;

        // ---- parallel idxs writes: thread j handles member j ----
        if (t < B && (NBOX + step + t) < out_size)
            out[NBOX + step + t] = (float)g_orig[sbatch_meta[t].x];

        // ---- apply batch decay with 2D thread window (exact-conservative) -
        for (int j = 0; j < B; j++) {
            const float4 mb = sbatch_box[j];       // LDS broadcast
            if (mb.x <= tx2hi && mb.z >= tx1lo &&
                mb.y <= ty2hi && mb.w >= ty1lo) {
                const uint2 mm  = sbatch_meta[j];
                const float mar = (mb.z - mb.x) * (mb.w - mb.y);
#pragma unroll
                for (int k = 0; k < PER; k++) {
                    if ((procm >> k) & 1u) continue;
                    if (t * PER + k == (int)mm.x) {
                        procm |= 1u << k;
                        if (orig[k] < out_size) out[orig[k]] = __uint_as_float(mm.y);
                        dirty = true;
                    } else {
                        const float iw = fmaxf(fminf(mb.z, x2[k]) - fmaxf(mb.x, x1[k]), 0.0f);
                        const float ih = fmaxf(fminf(mb.w, y2[k]) - fmaxf(mb.y, y1[k]), 0.0f);
                        const float inter = iw * ih;
                        if (inter > 0.0f) {
                            const float iou = __fdividef(inter, mar + area[k] - inter);
                            s[k] *= __expf(-2.0f * iou * iou);
                            dirty = true;
                        }
                    }
                }
            }
        }
        step += B;
        if (sfro) { fro_final = 1; fpos_final = sfpos; break; }
    }

    // ---- frozen tail: all remaining steps re-select the same argmax ----
    if (fro_final && step < NBOX) {
        const int fo = g_orig[fpos_final];
        for (int j = step + t; j < NBOX; j += T) {
            if ((NBOX + j) < out_size) out[NBOX + j] = (float)fo;
        }
    }
}

extern "C" void kernel_launch(void* const* d_in, const int* in_sizes, int n_in,
                              void* d_out, int out_size)
{
    const float4* boxes;
    const float*  scores;
    if (in_sizes[0] == 4 * NBOX) {
        boxes  = (const float4*)d_in[0];
        scores = (const float*)d_in[1];
    } else {
        boxes  = (const float4*)d_in[1];
        scores = (const float*)d_in[0];
    }
    softnms_kernel<<<1, T>>>(boxes, scores, (float*)d_out, out_size);
}

// round 16
// speedup vs baseline: 1.0171x; 1.0072x over previous
#include <cuda_runtime.h>

#define NBOX 4096
#define T 1024
#define PER 4                  // NBOX / T
#define NWARP 32
#define PROD (NWARP - 1)       // producer = HIGHEST wid (hi-wid-first arbiter)
#define BMAX 64
#define THRESH 0.05f
#define FULL 0xffffffffu

__device__ float4 g_sbox[NBOX];
__device__ int    g_orig[NBOX];

__global__ __launch_bounds__(T, 1)
void softnms_kernel(const float4* __restrict__ boxes,
                    const float*  __restrict__ scores,
                    float* __restrict__ out, int out_size)
{
    __shared__ unsigned long long skv[NBOX];   // sort scratch
    __shared__ uint4    spoolA[NWARP];         // (k1, p1, k2, p2) exact keys
    __shared__ unsigned sm3[NWARP];            // per-warp 3rd-best value
    __shared__ float4   sbatch_box[BMAX];
    __shared__ uint2    sbatch_meta[BMAX];     // (sorted pos, exact score bits)
    __shared__ int      sB, sfro, sfpos;

    const int t    = threadIdx.x;
    const int lane = t & 31;
    const int wid  = t >> 5;

    // ---- init: zero score outputs, stage u64 sort keys ----
#pragma unroll
    for (int k = 0; k < PER; k++) {
        const int gi = t * PER + k;
        if (gi < out_size) out[gi] = 0.0f;
        skv[gi] = ((unsigned long long)__float_as_uint(boxes[gi].x) << 32)
                  | (unsigned)gi;
    }
    __syncthreads();

    // ---- bitonic sort ascending by x1 ----
    for (int k = 2; k <= NBOX; k <<= 1) {
        for (int j = k >> 1; j > 0; j >>= 1) {
#pragma unroll
            for (int e = t; e < NBOX; e += T) {
                const int ixj = e ^ j;
                if (ixj > e) {
                    const unsigned long long a = skv[e], c = skv[ixj];
                    const bool up = ((e & k) == 0);
                    if (up ? (a > c) : (a < c)) { skv[e] = c; skv[ixj] = a; }
                }
            }
            __syncthreads();
        }
    }

    // ---- load my PER sorted boxes; publish sorted tables ----
    float x1[PER], y1[PER], x2[PER], y2[PER], area[PER], s[PER];
    int   orig[PER];
    unsigned procm = 0;
    float tx2hi = 0.0f;
#pragma unroll
    for (int k = 0; k < PER; k++) {
        const int pos = t * PER + k;
        const int o   = (int)(unsigned)(skv[pos] & 0xffffffffu);
        orig[k] = o;
        const float4 b = boxes[o];
        x1[k] = b.x; y1[k] = b.y; x2[k] = b.z; y2[k] = b.w;
        area[k] = (b.z - b.x) * (b.w - b.y);
        s[k]    = scores[o];
        g_sbox[pos] = b;
        g_orig[pos] = o;
        tx2hi = fmaxf(tx2hi, b.z);
    }
    const float tx1lo = x1[0];
    __syncthreads();

    bool dirty = true;
    int  step  = 0;
    int  fro_final = 0, fpos_final = 0;

    while (step < NBOX) {
        // ========= rebuild per-warp top-2 (+3rd value), EXACT argmax =======
        if (__ballot_sync(FULL, dirty)) {
            unsigned b1 = 0, b2 = 0, b3 = 0, p1 = 0, p2 = 0;
#pragma unroll
            for (int k = 0; k < PER; k++) {
                if (!((procm >> k) & 1u)) {
                    const unsigned ub = __float_as_uint(s[k]);   // scores > 0
                    const unsigned up = (unsigned)(t * PER + k);
                    if (ub > b1)      { b3 = b2; b2 = b1; p2 = p1; b1 = ub; p1 = up; }
                    else if (ub > b2) { b3 = b2; b2 = ub; p2 = up; }
                    else if (ub > b3) { b3 = ub; }
                }
            }
            const unsigned m1   = __reduce_max_sync(FULL, b1);
            const unsigned bal1 = __ballot_sync(FULL, b1 == m1);
            const int s1        = __ffs(bal1) - 1;
            const unsigned q1   = __shfl_sync(FULL, p1, s1);
            const unsigned v2   = (lane == s1) ? b2 : b1;
            const unsigned vp2  = (lane == s1) ? p2 : p1;
            const unsigned m2   = __reduce_max_sync(FULL, v2);
            const unsigned bal2 = __ballot_sync(FULL, v2 == m2);
            const int s2        = __ffs(bal2) - 1;
            const unsigned q2   = __shfl_sync(FULL, vp2, s2);
            unsigned v3 = b1;
            if (lane == s1) v3 = b2;
            if (lane == s2) v3 = (s2 == s1) ? b3 : b2;
            const unsigned m3 = __reduce_max_sync(FULL, v3);
            if (lane == 0) { spoolA[wid] = make_uint4(m1, q1, m2, q2); sm3[wid] = m3; }
            dirty = false;
        }
        __syncthreads();   // bar1: pools visible; consumers park in bar2 next

        if (wid == PROD) {
            // ==== producer: DUAL-ACCEPT batch scan on a quiet SM ===========
            const uint4 a = spoolA[lane];
            unsigned k1 = a.x, pp1 = a.y, k2 = a.z, pp2 = a.w;
            const unsigned M3 = __reduce_max_sync(FULL, sm3[lane]);
            const float4 f1 = g_sbox[pp1]; const float a1 = (f1.z - f1.x) * (f1.w - f1.y);
            const float4 f2 = g_sbox[pp2]; const float a2 = (f2.z - f2.x) * (f2.w - f2.y);
            const unsigned THRESH_BITS = __float_as_uint(THRESH);

            int B = 0, fz = 0; unsigned fp = 0;
            while (true) {
                const bool s1w      = (k1 >= k2);
                const unsigned kmax = s1w ? k1 : k2;
                const unsigned mA   = __reduce_max_sync(FULL, kmax);
                if (mA < M3) break;                  // pool no longer covers order
                const unsigned balA = __ballot_sync(FULL, kmax == mA);
                const int srcA      = __ffs(balA) - 1;
                if (mA <= THRESH_BITS) {             // pool max == global max
                    fz = 1;
                    fp = __shfl_sync(FULL, s1w ? pp1 : pp2, srcA);
                    break;
                }
                const bool isA = (lane == srcA);
                // global #2: demote srcA's winning slot to its other slot
                const unsigned v2  = isA ? (s1w ? k2 : k1) : kmax;
                const bool   v2k1  = isA ? !s1w : s1w;
                const unsigned mB  = __reduce_max_sync(FULL, v2);
                const unsigned balB = __ballot_sync(FULL, v2 == mB);
                const int srcB      = __ffs(balB) - 1;
                const bool isB = (lane == srcB);

                // coords for A and B (parallel shfls from winners' registers)
                const float ax1 = __shfl_sync(FULL, s1w ? f1.x : f2.x, srcA);
                const float ay1 = __shfl_sync(FULL, s1w ? f1.y : f2.y, srcA);
                const float ax2 = __shfl_sync(FULL, s1w ? f1.z : f2.z, srcA);
                const float ay2 = __shfl_sync(FULL, s1w ? f1.w : f2.w, srcA);
                const float bx1 = __shfl_sync(FULL, v2k1 ? f1.x : f2.x, srcB);
                const float by1 = __shfl_sync(FULL, v2k1 ? f1.y : f2.y, srcB);
                const float bx2 = __shfl_sync(FULL, v2k1 ? f1.z : f2.z, srcB);
                const float by2 = __shfl_sync(FULL, v2k1 ? f1.w : f2.w, srcB);
                const float marA = (ax2 - ax1) * (ay2 - ay1);

                // A-B overlap (warp-uniform): B acceptable only if disjoint
                const bool ovAB =
                    (fminf(ax2, bx2) > fmaxf(ax1, bx1)) &&
                    (fminf(ay2, by2) > fmaxf(ay1, by1));
                const bool accB = (!ovAB) && (mB >= M3) && (mB > THRESH_BITS)
                                  && (B + 2 <= BMAX);

                if (isA) {                           // plain STS; bar2 publishes
                    sbatch_box[B]  = make_float4(ax1, ay1, ax2, ay2);
                    sbatch_meta[B] = make_uint2(s1w ? pp1 : pp2, mA);
                }
                if (accB && isB) {
                    sbatch_box[B + 1]  = make_float4(bx1, by1, bx2, by2);
                    sbatch_meta[B + 1] = make_uint2(v2k1 ? pp1 : pp2, mB);
                }
                // consume winners' slots (0 stays 0 through decays)
                k1 = (isA &&  s1w) ? 0u : k1;
                k2 = (isA && !s1w) ? 0u : k2;
                k1 = (accB && isB &&  v2k1) ? 0u : k1;
                k2 = (accB && isB && !v2k1) ? 0u : k2;
                // decay by A (bit-exact, unconditional)
                {
                    const float iw = fmaxf(fminf(ax2, f1.z) - fmaxf(ax1, f1.x), 0.0f);
                    const float ih = fmaxf(fminf(ay2, f1.w) - fmaxf(ay1, f1.y), 0.0f);
                    const float inter = iw * ih;
                    const float iou = __fdividef(inter, marA + a1 - inter);
                    k1 = __float_as_uint(__uint_as_float(k1) * __expf(-2.0f * iou * iou));
                }
                {
                    const float iw = fmaxf(fminf(ax2, f2.z) - fmaxf(ax1, f2.x), 0.0f);
                    const float ih = fmaxf(fminf(ay2, f2.w) - fmaxf(ay1, f2.y), 0.0f);
                    const float inter = iw * ih;
                    const float iou = __fdividef(inter, marA + a2 - inter);
                    k2 = __float_as_uint(__uint_as_float(k2) * __expf(-2.0f * iou * iou));
                }
                // decay by B (only when B accepted; warp-uniform branch)
                if (accB) {
                    const float marB = (bx2 - bx1) * (by2 - by1);
                    {
                        const float iw = fmaxf(fminf(bx2, f1.z) - fmaxf(bx1, f1.x), 0.0f);
                        const float ih = fmaxf(fminf(by2, f1.w) - fmaxf(by1, f1.y), 0.0f);
                        const float inter = iw * ih;
                        const float iou = __fdividef(inter, marB + a1 - inter);
                        k1 = __float_as_uint(__uint_as_float(k1) * __expf(-2.0f * iou * iou));
                    }
                    {
                        const float iw = fmaxf(fminf(bx2, f2.z) - fmaxf(bx1, f2.x), 0.0f);
                        const float ih = fmaxf(fminf(by2, f2.w) - fmaxf(by1, f2.y), 0.0f);
                        const float inter = iw * ih;
                        const float iou = __fdividef(inter, marB + a2 - inter);
                        k2 = __float_as_uint(__uint_as_float(k2) * __expf(-2.0f * iou * iou));
                    }
                }
                B += accB ? 2 : 1;
                if (B >= BMAX) break;
            }
            if (lane == 0) { sB = B; sfro = fz; sfpos = (int)fp; }
        }
        __syncthreads();   // bar2: batch + flags visible to everyone

        const int B = sB;

        // ---- parallel idxs writes: thread j handles member j ----
        if (t < B && (NBOX + step + t) < out_size)
            out[NBOX + step + t] = (float)g_orig[sbatch_meta[t].x];

        // ---- apply batch decay: my PER boxes vs all B members ----
        for (int j = 0; j < B; j++) {
            const float4 mb = sbatch_box[j];       // LDS broadcast
            if (mb.x <= tx2hi && mb.z >= tx1lo) {  // x-interval skip (exact)
                const uint2 mm  = sbatch_meta[j];
                const float mar = (mb.z - mb.x) * (mb.w - mb.y);
#pragma unroll
                for (int k = 0; k < PER; k++) {
                    if ((procm >> k) & 1u) continue;
                    if (t * PER + k == (int)mm.x) {
                        procm |= 1u << k;
                        if (orig[k] < out_size) out[orig[k]] = __uint_as_float(mm.y);
                        dirty = true;
                    } else {
                        const float iw = fmaxf(fminf(mb.z, x2[k]) - fmaxf(mb.x, x1[k]), 0.0f);
                        const float ih = fmaxf(fminf(mb.w, y2[k]) - fmaxf(mb.y, y1[k]), 0.0f);
                        const float inter = iw * ih;
                        if (inter > 0.0f) {
                            const float iou = __fdividef(inter, mar + area[k] - inter);
                            s[k] *= __expf(-2.0f * iou * iou);
                            dirty = true;
                        }
                    }
                }
            }
        }
        step += B;
        if (sfro) { fro_final = 1; fpos_final = sfpos; break; }
    }

    // ---- frozen tail: all remaining steps re-select the same argmax ----
    if (fro_final && step < NBOX) {
        const int fo = g_orig[fpos_final];
        for (int j = step + t; j < NBOX; j += T) {
            if ((NBOX + j) < out_size) out[NBOX + j] = (float)fo;
        }
    }
}

extern "C" void kernel_launch(void* const* d_in, const int* in_sizes, int n_in,
                              void* d_out, int out_size)
{
    const float4* boxes;
    const float*  scores;
    if (in_sizes[0] == 4 * NBOX) {
        boxes  = (const float4*)d_in[0];
        scores = (const float*)d_in[1];
    } else {
        boxes  = (const float4*)d_in[1];
        scores = (const float*)d_in[0];
    }
    softnms_kernel<<<1, T>>>(boxes, scores, (float*)d_out, out_size);
}